// round 9
// baseline (speedup 1.0000x reference)
#include <cuda_runtime.h>
#include <stdint.h>

#define Bc    64
#define CIN   256
#define COUT  256
#define HW    28
#define NPIX  (HW*HW)            // 784
#define NW    (COUT*CIN*9)       // 589824
#define KK    8
#define PDIM  30
#define PPIX  (PDIM*PDIM)        // 900
#define PROWS 960

#define NB_POP  44               // images 0..43 -> popc path
#define NB_IMMA 20               // images 44..63 -> imma path
#define NPOP_CTA (NB_POP * 7)    // 308 (4-row bands)
#define NIMMA_CTA (NB_IMMA * 14) // 280 (7 mtiles x 2 nh)

// ---------------- device scratch ----------------
__device__ __align__(16) uint32_t g_w[COUT * 9 * 8];            // popc weights
__device__ int                    g_corr[COUT * 9];
__device__ __align__(16) uint32_t g_pabits[(size_t)NB_POP * PPIX * 8];
__device__ __align__(1024) uint8_t g_act[(size_t)NB_IMMA * PROWS * CIN]; // s8, swizzled
__device__ __align__(1024) uint8_t g_wB[(size_t)18 * 256 * 128];         // s8 planes

// ---------------- helpers ----------------
__device__ __forceinline__ uint32_t smem_u32(const void* p) {
    uint32_t a;
    asm("{ .reg .u64 t; cvta.to.shared.u64 t, %1; cvt.u32.u64 %0, t; }" : "=r"(a) : "l"(p));
    return a;
}
__device__ __forceinline__ void mbar_init(uint32_t mb, uint32_t cnt) {
    asm volatile("mbarrier.init.shared.b64 [%0], %1;" :: "r"(mb), "r"(cnt) : "memory");
}
__device__ __forceinline__ void mbar_expect_tx(uint32_t mb, uint32_t bytes) {
    asm volatile("mbarrier.arrive.expect_tx.shared.b64 _, [%0], %1;" :: "r"(mb), "r"(bytes) : "memory");
}
__device__ __forceinline__ void mbar_wait(uint32_t mb, uint32_t parity) {
    asm volatile(
        "{\n.reg .pred P1;\n"
        "LAB_WAIT_%=:\n"
        "mbarrier.try_wait.parity.acquire.cta.shared::cta.b64 P1, [%0], %1, 0x989680;\n"
        "@P1 bra.uni LAB_DONE_%=;\n"
        "bra.uni LAB_WAIT_%=;\n"
        "LAB_DONE_%=:\n}\n" :: "r"(mb), "r"(parity) : "memory");
}
__device__ __forceinline__ void bulk_g2s(uint32_t dst, const void* src, uint32_t bytes, uint32_t mb) {
    asm volatile("cp.async.bulk.shared::cta.global.mbarrier::complete_tx::bytes [%0], [%1], %2, [%3];"
                 :: "r"(dst), "l"(src), "r"(bytes), "r"(mb) : "memory");
}
__device__ __forceinline__ void ldsm4(uint32_t* r, uint32_t addr) {
    asm volatile("ldmatrix.sync.aligned.m8n8.x4.shared.b16 {%0,%1,%2,%3}, [%4];"
                 : "=r"(r[0]), "=r"(r[1]), "=r"(r[2]), "=r"(r[3]) : "r"(addr));
}
__device__ __forceinline__ void imma16832(int* d, const uint32_t* a, uint32_t b0, uint32_t b1) {
    asm volatile("mma.sync.aligned.m16n8k32.row.col.s32.s8.s8.s32 "
                 "{%0,%1,%2,%3}, {%4,%5,%6,%7}, {%8,%9}, {%0,%1,%2,%3};"
                 : "+r"(d[0]), "+r"(d[1]), "+r"(d[2]), "+r"(d[3])
                 : "r"(a[0]), "r"(a[1]), "r"(a[2]), "r"(a[3]), "r"(b0), "r"(b1));
}

// ---------------------------------------------------------------------------
// Kernel 1a: popc weights (coalesced loads + smem transpose + ballot pack)
// ---------------------------------------------------------------------------
__global__ void wbits_kernel(const float* __restrict__ M, const float* __restrict__ Z,
                             const float* __restrict__ rv)
{
    __shared__ float swv[2304];
    __shared__ int   sP[9];
    const int o    = blockIdx.x;
    const int c    = threadIdx.x;
    const int lane = c & 31;
    const int cw   = c >> 5;

    if (c < 9) sP[c] = 0;

    float rvl[KK];
#pragma unroll
    for (int k = 0; k < KK; k++) rvl[k] = __ldg(rv + k);

    float wv9[9];
    {
        const float* Mp = M + (size_t)o * 2304;
#pragma unroll
        for (int i = 0; i < 9; i++) wv9[i] = Mp[i * 256 + c];
#pragma unroll
        for (int k = 0; k < KK; k++) {
            const float* zp = Z + (size_t)k * NW + (size_t)o * 2304;
#pragma unroll
            for (int i = 0; i < 9; i++) wv9[i] += rvl[k] * zp[i * 256 + c];
        }
    }
#pragma unroll
    for (int i = 0; i < 9; i++) swv[i * 256 + c] = wv9[i];
    __syncthreads();

#pragma unroll
    for (int j = 0; j < 9; j++) {
        unsigned bit  = __float_as_uint(swv[c * 9 + j]) >> 31;
        unsigned mask = __ballot_sync(0xffffffffu, bit);
        if (lane == 0) {
            g_w[(o * 9 + j) * 8 + cw] = mask;
            atomicAdd(&sP[j], __popc(mask));
        }
    }
    __syncthreads();
    if (c < 9) g_corr[o * 9 + c] = 256 - 2 * sP[c];
}

// ---------------------------------------------------------------------------
// Kernel 1b: imma weights -> s8 plane layout (pre-swizzled), as in R5
// ---------------------------------------------------------------------------
__global__ void wconv_kernel(const float* __restrict__ M, const float* __restrict__ Z,
                             const float* __restrict__ rv)
{
    const int gid = blockIdx.x * 256 + threadIdx.x;
    float rvl[KK];
#pragma unroll
    for (int k = 0; k < KK; k++) rvl[k] = __ldg(rv + k);

    const int idx4 = gid * 4;
    float4 w4 = *(const float4*)(M + idx4);
#pragma unroll
    for (int k = 0; k < KK; k++) {
        float4 z4 = *(const float4*)(Z + (size_t)k * NW + idx4);
        w4.x += rvl[k] * z4.x; w4.y += rvl[k] * z4.y;
        w4.z += rvl[k] * z4.z; w4.w += rvl[k] * z4.w;
    }
    float wv[4] = {w4.x, w4.y, w4.z, w4.w};
#pragma unroll
    for (int e4 = 0; e4 < 4; e4++) {
        int flat = idx4 + e4;
        int o = flat / 2304;
        int rem = flat - o * 2304;
        int c = rem / 9;
        int t = rem - c * 9;
        uint32_t s = __float_as_uint(wv[e4]) >> 31;
        const int h    = c >> 7;
        const int kc16 = (c >> 4) & 7;
        const int e    = c & 15;
        g_wB[((size_t)((t * 2 + h) * 256 + o)) * 128
             + (uint32_t)(((kc16 ^ (o & 7)) << 4) + e)] = (uint8_t)(0x01u + s * 0xFEu);
    }
}

// ---------------------------------------------------------------------------
// Kernel 2a: bit-packed padded activations, images [0, NB_POP)
// ---------------------------------------------------------------------------
__global__ void abits_kernel(const float* __restrict__ x)
{
    const int gid = blockIdx.x * 256 + threadIdx.x;
    if (gid >= NB_POP * PPIX) return;
    const int b  = gid / PPIX;
    const int pp = gid - b * PPIX;
    const int py = pp / PDIM;
    const int px = pp - py * PDIM;

    uint4* dst = (uint4*)(g_pabits + ((size_t)b * PPIX + pp) * 8);

    if (py == 0 || py == PDIM - 1 || px == 0 || px == PDIM - 1) {
        uint4 z = make_uint4(0, 0, 0, 0);
        dst[0] = z; dst[1] = z;
        return;
    }
    const float* xp = x + (size_t)b * CIN * NPIX + (py - 1) * HW + (px - 1);
    uint32_t w[8];
#pragma unroll
    for (int cw = 0; cw < 8; cw++) {
        uint32_t m = 0;
#pragma unroll
        for (int j = 0; j < 32; j++) {
            uint32_t s = __float_as_uint(xp[(size_t)(cw * 32 + j) * NPIX]) >> 31;
            m |= s << j;
        }
        w[cw] = m;
    }
    dst[0] = make_uint4(w[0], w[1], w[2], w[3]);
    dst[1] = make_uint4(w[4], w[5], w[6], w[7]);
}

// ---------------------------------------------------------------------------
// Kernel 2b: s8 padded activations (swizzled chunks), images [NB_POP, 64)
// ---------------------------------------------------------------------------
__global__ void aconv_kernel(const float* __restrict__ x)
{
    const int gid = blockIdx.x * 256 + threadIdx.x;
    if (gid >= NB_IMMA * PPIX) return;
    const int ib = gid / PPIX;                 // local image
    const int pp = gid - ib * PPIX;
    const int py = pp / PDIM;
    const int px = pp - py * PDIM;

    uint4* dst = (uint4*)(g_act + ((size_t)ib * PROWS + pp) * CIN);

    if (py == 0 || py == PDIM - 1 || px == 0 || px == PDIM - 1) {
        uint4 z = make_uint4(0, 0, 0, 0);
#pragma unroll
        for (int i = 0; i < 16; i++) dst[i] = z;
        return;
    }
    const int sw = pp & 7;
    const float* xp = x + (size_t)(NB_POP + ib) * CIN * NPIX + (py - 1) * HW + (px - 1);
#pragma unroll
    for (int cw = 0; cw < 16; cw++) {
        uint32_t wds[4];
#pragma unroll
        for (int q = 0; q < 4; q++) {
            uint32_t wd = 0;
#pragma unroll
            for (int e = 0; e < 4; e++) {
                int c = cw * 16 + q * 4 + e;
                uint32_t s = __float_as_uint(xp[(size_t)c * NPIX]) >> 31;
                wd |= (0x01u + s * 0xFEu) << (8 * e);
            }
            wds[q] = wd;
        }
        dst[cw ^ sw] = make_uint4(wds[0], wds[1], wds[2], wds[3]);
    }
}

// ---------------------------------------------------------------------------
// Kernel 3: hybrid conv. Interleaved CTAs: popc bands + imma GEMM tiles.
// grid <<<588, 256, 82560>>>
// ---------------------------------------------------------------------------
#define PSM_ABITS 0
#define PSM_STAGE 5760
// imma smem map (R5)
#define SM_A     0
#define SM_B0    49152
#define SM_B1    65536
#define SM_ALPHA 81920
#define SM_MBAR  82432
#define SM_TOTAL 82560

#define P8(A0, A1, W0, W1) \
    (__popc((A0).x ^ (W0).x) + __popc((A0).y ^ (W0).y) + \
     __popc((A0).z ^ (W0).z) + __popc((A0).w ^ (W0).w) + \
     __popc((A1).x ^ (W1).x) + __popc((A1).y ^ (W1).y) + \
     __popc((A1).z ^ (W1).z) + __popc((A1).w ^ (W1).w))

__global__ void __launch_bounds__(256)
conv_hybrid_kernel(const float* __restrict__ alpha, float* __restrict__ out)
{
    extern __shared__ __align__(1024) uint8_t smem[];
    const int tid  = threadIdx.x;
    const int wid  = tid >> 5;
    const int lane = tid & 31;
    const int idx  = blockIdx.x;

    // interleave: first 560 alternate popc/imma, tail 28 are popc
    const bool is_imma = (idx < 2 * NIMMA_CTA) && (idx & 1);
    const int  job     = (idx < 2 * NIMMA_CTA) ? (idx >> 1) : (NIMMA_CTA + idx - 2 * NIMMA_CTA);

    if (!is_imma) {
        // ================= popc path (R7 structure, 4-row band) =============
        const int b      = job / 7;
        const int blkrow = job - b * 7;
        const int r0     = blkrow * 4;

        {
            const uint4* src = (const uint4*)(g_pabits + ((size_t)b * PPIX + r0 * PDIM) * 8);
            uint4* d4 = (uint4*)(smem + PSM_ABITS);
            for (int i = tid; i < 6 * PDIM * 2; i += 256) d4[i] = src[i];
        }

        const int o = wid * 32 + lane;
        int corr[9];
#pragma unroll
        for (int t = 0; t < 9; t++) corr[t] = __ldg(g_corr + o * 9 + t);
        const float av = __ldg(alpha + o);
        const uint4* wbase = (const uint4*)(g_w + o * 72);

        __syncthreads();

        float* stage = (float*)(smem + PSM_STAGE) + wid * (32 * 29);
        const uint32_t* ab = (const uint32_t*)(smem + PSM_ABITS);

        for (int ry = 0; ry < 4; ry++) {
            const int y = r0 + ry;
            int acc[28];
#pragma unroll
            for (int x = 0; x < 28; x++) acc[x] = 0;

            const uint4* wp = wbase;
#pragma unroll 1
            for (int kh = 0; kh < 3; kh++) {
#pragma unroll 1
                for (int kw = 0; kw < 3; kw++) {
                    const uint4* rowp = (const uint4*)(ab + ((ry + kh) * PDIM + kw) * 8);
                    const uint4 w0 = __ldg(wp);
                    const uint4 w1 = __ldg(wp + 1);
                    wp += 2;
#pragma unroll
                    for (int x = 0; x < 28; x++) {
                        const uint4 a0 = rowp[x * 2];
                        const uint4 a1 = rowp[x * 2 + 1];
                        acc[x] += P8(a0, a1, w0, w1);
                    }
                }
            }

            const int rowc = (y == 0)  ? (corr[0] + corr[1] + corr[2])
                           : (y == 27) ? (corr[6] + corr[7] + corr[8]) : 0;
            int c0  = corr[0] + corr[3] + corr[6];
            int c27 = corr[2] + corr[5] + corr[8];
            if (y == 0)  { c0 -= corr[0]; c27 -= corr[2]; }
            if (y == 27) { c0 -= corr[6]; c27 -= corr[8]; }

#pragma unroll
            for (int x = 0; x < 28; x++) {
                int cs = rowc;
                if (x == 0)  cs += c0;
                if (x == 27) cs += c27;
                stage[lane * 29 + x] = av * (float)(2304 - 2 * acc[x] - cs);
            }

            __syncwarp();
            float* outb = out + ((size_t)(b * COUT + wid * 32) * HW + y) * HW;
            if (lane < HW) {
#pragma unroll 4
                for (int oo = 0; oo < 32; oo++)
                    outb[(size_t)oo * NPIX + lane] = stage[oo * 29 + lane];
            }
            __syncwarp();
        }
        return;
    }

    // ================= imma path (R5 structure, bulk staging) ===============
    const uint32_t sb = smem_u32(smem);
    const int wm = wid & 3;
    const int wn = wid >> 2;

    const int nh    = job & 1;
    const int bm    = job >> 1;
    const int ib    = bm / 7;                  // local image
    const int mtile = bm - ib * 7;
    const int tbase = mtile * 128;
    const int bglob = NB_POP + ib;

    const uint32_t mbA = sb + SM_MBAR;
    const uint32_t mbB = sb + SM_MBAR + 8;

    float* salpha = (float*)(smem + SM_ALPHA);
    if (tid == 0) { mbar_init(mbA, 1); mbar_init(mbB, 1); mbar_init(mbB + 8, 1); }
    if (tid < 128) salpha[tid] = __ldg(alpha + nh * 128 + tid);
    __syncthreads();

    if (tid == 0) {
        mbar_expect_tx(mbA, 190 * 256);
        bulk_g2s(sb + SM_A, g_act + ((size_t)ib * PROWS + tbase) * 256, 190 * 256, mbA);
        mbar_expect_tx(mbB, 16384);
        bulk_g2s(sb + SM_B0, g_wB + (size_t)(nh * 128) * 128, 16384, mbB);
    }

    int acc[2][8][4];
#pragma unroll
    for (int mf = 0; mf < 2; mf++)
#pragma unroll
        for (int nf = 0; nf < 8; nf++)
#pragma unroll
            for (int j = 0; j < 4; j++) acc[mf][nf][j] = 0;

    const int lrow = lane & 15;
    const int lhi4 = lane >> 4;

    for (int p = 0; p < 18; ++p) {
        const int buf = p & 1;
        if (p < 17 && tid == 0) {
            const int pn = p + 1;
            const uint32_t mb = mbB + (pn & 1) * 8;
            mbar_expect_tx(mb, 16384);
            bulk_g2s(sb + ((pn & 1) ? SM_B1 : SM_B0),
                     g_wB + (size_t)(pn * 256 + nh * 128) * 128, 16384, mb);
        }
        mbar_wait(mbB + buf * 8, (p >> 1) & 1);
        if (p == 0) mbar_wait(mbA, 0);

        const int t = p >> 1, h = p & 1;
        const int toff = (t / 3) * PDIM + (t % 3);
        const uint32_t bb = sb + (buf ? SM_B1 : SM_B0);

#pragma unroll
        for (int ks = 0; ks < 4; ks++) {
            uint32_t a[2][4];
#pragma unroll
            for (int mf = 0; mf < 2; mf++) {
                const int row = toff + wm * 32 + mf * 16 + lrow;
                const int c16 = h * 8 + ks * 2 + lhi4;
                ldsm4(a[mf], sb + SM_A + row * 256 + ((c16 ^ (row & 7)) << 4));
            }
            uint32_t bf[4][4];
#pragma unroll
            for (int bg = 0; bg < 4; bg++) {
                const int o  = wn * 64 + bg * 16 + lrow;
                const int kc = ks * 2 + lhi4;
                ldsm4(bf[bg], bb + o * 128 + ((kc ^ (o & 7)) << 4));
            }
#pragma unroll
            for (int mf = 0; mf < 2; mf++)
#pragma unroll
                for (int nf = 0; nf < 8; nf++)
                    imma16832(acc[mf][nf], a[mf],
                              bf[nf >> 1][nf & 1], bf[nf >> 1][(nf & 1) + 2]);
        }
        __syncthreads();
    }

    const int pixr  = tbase + wm * 32;
    const int oloc  = wn * 64 + (lane & 3) * 2;
    const int oglob = nh * 128 + oloc;
    float* outb = out + (size_t)bglob * COUT * NPIX;

#pragma unroll
    for (int mf = 0; mf < 2; mf++) {
        const int rb = pixr + mf * 16 + (lane >> 2);
#pragma unroll
        for (int half = 0; half < 2; half++) {
            const int row = rb + half * 8;
            const int y  = row / PDIM;
            const int xx = row - y * PDIM;
            if (xx < HW && y < HW) {
                float* op = outb + y * HW + xx;
#pragma unroll
                for (int nf = 0; nf < 8; nf++) {
                    const int ol = oloc + nf * 8;
                    const int og = oglob + nf * 8;
                    op[(size_t)og * NPIX]       = salpha[ol]     * (float)acc[mf][nf][half * 2];
                    op[(size_t)(og + 1) * NPIX] = salpha[ol + 1] * (float)acc[mf][nf][half * 2 + 1];
                }
            }
        }
    }
}

// ---------------------------------------------------------------------------
extern "C" void kernel_launch(void* const* d_in, const int* in_sizes, int n_in,
                              void* d_out, int out_size)
{
    const float* x  = (const float*)d_in[0];
    const float* M  = (const float*)d_in[1];
    const float* Z  = (const float*)d_in[2];
    const float* al = (const float*)d_in[3];
    const float* rv = (const float*)d_in[4];

    cudaFuncSetAttribute(conv_hybrid_kernel,
                         cudaFuncAttributeMaxDynamicSharedMemorySize, SM_TOTAL);

    wbits_kernel<<<COUT, CIN>>>(M, Z, rv);
    wconv_kernel<<<576, 256>>>(M, Z, rv);
    abits_kernel<<<(NB_POP * PPIX + 255) / 256, 256>>>(x);
    aconv_kernel<<<(NB_IMMA * PPIX + 255) / 256, 256>>>(x);
    conv_hybrid_kernel<<<NPOP_CTA + NIMMA_CTA, 256, SM_TOTAL>>>(al, (float*)d_out);
}

// round 10
// speedup vs baseline: 1.1690x; 1.1690x over previous
#include <cuda_runtime.h>
#include <stdint.h>

#define Bc    64
#define CIN   256
#define COUT  256
#define HW    28
#define NPIX  (HW*HW)            // 784
#define NW    (COUT*CIN*9)       // 589824
#define KK    8
#define PDIM  30
#define PPIX  (PDIM*PDIM)        // 900

// ---------------- device scratch ----------------
__device__ __align__(16) uint32_t g_w[COUT * 9 * 8];          // [o][t][cw] sign bits
__device__ int                    g_corr[COUT * 9];           // 256 - 2*popc(w[o][t])
__device__ __align__(16) uint32_t g_pabits[(size_t)Bc * PPIX * 8]; // padded bit image

// ---------------------------------------------------------------------------
// Kernel 1: fused prep. Blocks [0,256): weights; [256,481): activations.
// grid <<<481, 256>>>
// ---------------------------------------------------------------------------
__global__ void prep_kernel(const float* __restrict__ M, const float* __restrict__ Z,
                            const float* __restrict__ rv, const float* __restrict__ x)
{
    __shared__ float swv[2304];
    __shared__ int   sP[9];

    if (blockIdx.x < COUT) {
        // ---- weights: coalesced loads + smem transpose + ballot pack ----
        const int o    = blockIdx.x;
        const int c    = threadIdx.x;
        const int lane = c & 31;
        const int cw   = c >> 5;

        if (c < 9) sP[c] = 0;

        float rvl[KK];
#pragma unroll
        for (int k = 0; k < KK; k++) rvl[k] = __ldg(rv + k);

        float wv9[9];
        {
            const float* Mp = M + (size_t)o * 2304;
#pragma unroll
            for (int i = 0; i < 9; i++) wv9[i] = Mp[i * 256 + c];
#pragma unroll
            for (int k = 0; k < KK; k++) {
                const float* zp = Z + (size_t)k * NW + (size_t)o * 2304;
#pragma unroll
                for (int i = 0; i < 9; i++) wv9[i] += rvl[k] * zp[i * 256 + c];
            }
        }
#pragma unroll
        for (int i = 0; i < 9; i++) swv[i * 256 + c] = wv9[i];
        __syncthreads();

#pragma unroll
        for (int j = 0; j < 9; j++) {
            unsigned bit  = __float_as_uint(swv[c * 9 + j]) >> 31;
            unsigned mask = __ballot_sync(0xffffffffu, bit);
            if (lane == 0) {
                g_w[(o * 9 + j) * 8 + cw] = mask;
                atomicAdd(&sP[j], __popc(mask));
            }
        }
        __syncthreads();
        if (c < 9) g_corr[o * 9 + c] = 256 - 2 * sP[c];
        return;
    }

    // ---- activations: zero-padded packed bit image [b][pp][8] ----
    const int gid = (blockIdx.x - COUT) * 256 + threadIdx.x;
    if (gid >= Bc * PPIX) return;
    const int b  = gid / PPIX;
    const int pp = gid - b * PPIX;
    const int py = pp / PDIM;
    const int px = pp - py * PDIM;

    uint4* dst = (uint4*)(g_pabits + ((size_t)b * PPIX + pp) * 8);

    if (py == 0 || py == PDIM - 1 || px == 0 || px == PDIM - 1) {
        uint4 z = make_uint4(0, 0, 0, 0);
        dst[0] = z; dst[1] = z;
        return;
    }
    const float* xp = x + (size_t)b * CIN * NPIX + (py - 1) * HW + (px - 1);
    uint32_t w[8];
#pragma unroll
    for (int cw = 0; cw < 8; cw++) {
        uint32_t m = 0;
#pragma unroll
        for (int j = 0; j < 32; j++) {
            uint32_t s = __float_as_uint(xp[(size_t)(cw * 32 + j) * NPIX]) >> 31;
            m |= s << j;
        }
        w[cw] = m;
    }
    dst[0] = make_uint4(w[0], w[1], w[2], w[3]);
    dst[1] = make_uint4(w[4], w[5], w[6], w[7]);
}

// ---------------------------------------------------------------------------
// Kernel 2: XNOR-popcount conv, 7-row bands, row-structured inner loop.
// CTA = (image b, 7-row band). 8 warps; warp = 32-outch group, lane = outch.
// grid <<<256, 256, 38336>>>
// ---------------------------------------------------------------------------
#define SM_ABITS 0                      // 9 rows x 30 px x 32B = 8640
#define SM_STAGE 8640                   // 8 warps x 32 x 29 floats = 29696
#define SM_TOTAL (8640 + 29696)

#define P8(A0, A1, W0, W1) \
    (__popc((A0).x ^ (W0).x) + __popc((A0).y ^ (W0).y) + \
     __popc((A0).z ^ (W0).z) + __popc((A0).w ^ (W0).w) + \
     __popc((A1).x ^ (W1).x) + __popc((A1).y ^ (W1).y) + \
     __popc((A1).z ^ (W1).z) + __popc((A1).w ^ (W1).w))

__global__ void __launch_bounds__(256)
conv_pop_kernel(const float* __restrict__ alpha, float* __restrict__ out)
{
    extern __shared__ __align__(16) uint8_t smem[];

    const int tid  = threadIdx.x;
    const int wid  = tid >> 5;
    const int lane = tid & 31;

    const int b    = blockIdx.x >> 2;
    const int band = blockIdx.x & 3;
    const int r0   = band * 7;

    // cooperative load: padded rows r0..r0+8 (540 uint4, contiguous)
    {
        const uint4* src = (const uint4*)(g_pabits + ((size_t)b * PPIX + r0 * PDIM) * 8);
        uint4* d4 = (uint4*)(smem + SM_ABITS);
        for (int i = tid; i < 9 * PDIM * 2; i += 256) d4[i] = src[i];
    }

    const int o = wid * 32 + lane;
    int corr[9];
#pragma unroll
    for (int t = 0; t < 9; t++) corr[t] = __ldg(g_corr + o * 9 + t);
    const float av = __ldg(alpha + o);
    const uint4* wbase = (const uint4*)(g_w + o * 72);

    __syncthreads();

    const uint32_t* ab = (const uint32_t*)(smem + SM_ABITS);
    float* stage = (float*)(smem + SM_STAGE) + wid * (32 * 29);

#pragma unroll 1
    for (int ry = 0; ry < 7; ry++) {
        const int y = r0 + ry;

        int acc[28];
#pragma unroll
        for (int xx = 0; xx < 28; xx++) acc[xx] = 0;

#pragma unroll 1
        for (int kh = 0; kh < 3; kh++) {
            const uint4* wp = wbase + kh * 6;
            const uint4 w00 = __ldg(wp + 0), w01 = __ldg(wp + 1);   // kw=0
            const uint4 w10 = __ldg(wp + 2), w11 = __ldg(wp + 3);   // kw=1
            const uint4 w20 = __ldg(wp + 4), w21 = __ldg(wp + 5);   // kw=2
            const uint4* rowp = (const uint4*)(ab + (ry + kh) * PDIM * 8);
#pragma unroll
            for (int px = 0; px < 30; px++) {
                const uint4 a0 = rowp[px * 2];
                const uint4 a1 = rowp[px * 2 + 1];
                if (px < 28)             acc[px]     += P8(a0, a1, w00, w01);
                if (px >= 1 && px <= 28) acc[px - 1] += P8(a0, a1, w10, w11);
                if (px >= 2)             acc[px - 2] += P8(a0, a1, w20, w21);
            }
        }

        // pad corrections (row-uniform + column edges)
        const int rowc = (y == 0)  ? (corr[0] + corr[1] + corr[2])
                       : (y == 27) ? (corr[6] + corr[7] + corr[8]) : 0;
        int c0  = corr[0] + corr[3] + corr[6];
        int c27 = corr[2] + corr[5] + corr[8];
        if (y == 0)  { c0 -= corr[0]; c27 -= corr[2]; }
        if (y == 27) { c0 -= corr[6]; c27 -= corr[8]; }

#pragma unroll
        for (int xx = 0; xx < 28; xx++) {
            int cs = rowc;
            if (xx == 0)  cs += c0;
            if (xx == 27) cs += c27;
            stage[lane * 29 + xx] = av * (float)(2304 - 2 * acc[xx] - cs);
        }

        __syncwarp();
        float* outb = out + ((size_t)(b * COUT + wid * 32) * HW + y) * HW;
        if (lane < HW) {
#pragma unroll 4
            for (int oo = 0; oo < 32; oo++)
                outb[(size_t)oo * NPIX + lane] = stage[oo * 29 + lane];
        }
        __syncwarp();
    }
}

// ---------------------------------------------------------------------------
extern "C" void kernel_launch(void* const* d_in, const int* in_sizes, int n_in,
                              void* d_out, int out_size)
{
    const float* x  = (const float*)d_in[0];
    const float* M  = (const float*)d_in[1];
    const float* Z  = (const float*)d_in[2];
    const float* al = (const float*)d_in[3];
    const float* rv = (const float*)d_in[4];

    cudaFuncSetAttribute(conv_pop_kernel,
                         cudaFuncAttributeMaxDynamicSharedMemorySize, SM_TOTAL);

    prep_kernel<<<COUT + (Bc * PPIX + 255) / 256, 256>>>(M, Z, rv, x);
    conv_pop_kernel<<<Bc * 4, 256, SM_TOTAL>>>(al, (float*)d_out);
}